// round 13
// baseline (speedup 1.0000x reference)
#include <cuda_runtime.h>
#include <cuda.h>
#include <cuda_fp16.h>
#include <cstdint>
#include <math.h>

// ---------------- problem constants ----------------
constexpr int Bb = 4, Tt = 4096, Hdim = 1024;
constexpr int Mtot = Bb * Tt;                         // 16384
constexpr long long PLANE = (long long)Mtot * Hdim;   // 16,777,216
constexpr int NC = 128, LCc = 32;
constexpr int EPAD = 66;                              // even pad

// Scratch (device globals; allocation-free)
__device__ __align__(16) __half2 g_fv[PLANE];         // packed (f, v) per element
__device__ __align__(1024) __half g_xh[PLANE];        // fp16 x
__device__ __align__(1024) __half g_wh[3u * 1024 * 1024]; // fp16 Wf|Wi|Wh
__device__ float g_F [Bb * NC * Hdim];
__device__ float g_V [Bb * NC * Hdim];
__device__ float g_Hs[Bb * NC * Hdim];

// ---------------- PTX helpers (base sm_103 target only) ----------------
__device__ __forceinline__ uint32_t smem_u32(const void* p) {
    uint32_t a;
    asm("{ .reg .u64 t; cvta.to.shared.u64 t, %1; cvt.u32.u64 %0, t; }" : "=r"(a) : "l"(p));
    return a;
}
__device__ __forceinline__ void mbar_init(uint32_t a, uint32_t cnt) {
    asm volatile("mbarrier.init.shared.b64 [%0], %1;" :: "r"(a), "r"(cnt) : "memory");
}
__device__ __forceinline__ void mbar_arrive(uint32_t a) {
    asm volatile("mbarrier.arrive.shared.b64 _, [%0];" :: "r"(a) : "memory");
}
__device__ __forceinline__ void mbar_expect_tx(uint32_t a, uint32_t bytes) {
    asm volatile("mbarrier.arrive.expect_tx.shared.b64 _, [%0], %1;" :: "r"(a), "r"(bytes) : "memory");
}
__device__ __forceinline__ void mbar_wait(uint32_t a, uint32_t parity) {
    asm volatile(
        "{\n\t.reg .pred P;\n\t"
        "WL%=:\n\t"
        "mbarrier.try_wait.parity.acquire.cta.shared::cta.b64 P, [%0], %1, 0x989680;\n\t"
        "@!P bra WL%=;\n\t}"
        :: "r"(a), "r"(parity) : "memory");
}
__device__ __forceinline__ void tma_2d(uint32_t dst, const CUtensorMap* m, int x, int y, uint32_t mbar) {
    asm volatile(
        "cp.async.bulk.tensor.2d.shared::cta.global.tile.mbarrier::complete_tx::bytes "
        "[%0], [%1, {%2, %3}], [%4];"
        :: "r"(dst), "l"(m), "r"(x), "r"(y), "r"(mbar) : "memory");
}
__device__ __forceinline__ void ldsm4(uint32_t* r, uint32_t addr) {
    asm volatile("ldmatrix.sync.aligned.m8n8.x4.shared.b16 {%0,%1,%2,%3}, [%4];"
                 : "=r"(r[0]), "=r"(r[1]), "=r"(r[2]), "=r"(r[3]) : "r"(addr));
}
__device__ __forceinline__ void mma16(float* d, const uint32_t* a, uint32_t b0, uint32_t b1) {
    asm volatile(
        "mma.sync.aligned.m16n8k16.row.col.f32.f16.f16.f32 "
        "{%0,%1,%2,%3}, {%4,%5,%6,%7}, {%8,%9}, {%0,%1,%2,%3};"
        : "+f"(d[0]), "+f"(d[1]), "+f"(d[2]), "+f"(d[3])
        : "r"(a[0]), "r"(a[1]), "r"(a[2]), "r"(a[3]), "r"(b0), "r"(b1));
}
__device__ __forceinline__ uint32_t f2h2(float a, float b) {
    __half2 h = __floats2half2_rn(a, b);
    return *reinterpret_cast<uint32_t*>(&h);
}

// ---------------- scalar math ----------------
__device__ __forceinline__ float sigmf(float x) {
    float e = expf(-fabsf(x));
    return (x >= 0.0f) ? 1.0f / (1.0f + e) : e / (1.0f + e);
}

// ---------------- prep: convert inputs to fp16 ----------------
__global__ __launch_bounds__(256)
void cvt_x_kernel(const float4* __restrict__ in, int base) {
    const int g = base + blockIdx.x * 256 + threadIdx.x;   // 8-float groups
    const float4 v0 = in[2 * g];
    const float4 v1 = in[2 * g + 1];
    uint4 o;
    o.x = f2h2(v0.x, v0.y); o.y = f2h2(v0.z, v0.w);
    o.z = f2h2(v1.x, v1.y); o.w = f2h2(v1.z, v1.w);
    ((uint4*)g_xh)[g] = o;
}
__global__ __launch_bounds__(256)
void cvt_w_kernel(const float4* __restrict__ wf, const float4* __restrict__ wi,
                  const float4* __restrict__ wh) {
    const int g = blockIdx.x * 256 + threadIdx.x;          // 131072 groups per mat
    const float4* src[3] = {wf, wi, wh};
    #pragma unroll
    for (int mat = 0; mat < 3; mat++) {
        const float4 v0 = src[mat][2 * g];
        const float4 v1 = src[mat][2 * g + 1];
        uint4 o;
        o.x = f2h2(v0.x, v0.y); o.y = f2h2(v0.z, v0.w);
        o.z = f2h2(v1.x, v1.y); o.w = f2h2(v1.z, v1.w);
        ((uint4*)g_wh)[mat * 131072 + g] = o;
    }
}

// ---------------- fused GEMM (fp16 HMMA) + gates + chunk aggregates ----------------
// 4-stage ring, BK=32 halves, SW64 staging (64B rows). Stage = A 8K + 3x B 4K = 20K.
constexpr int STAGES = 4;
constexpr int STAGE_BYTES = 20480;
constexpr int S_DATA = 1024;
constexpr int SMEM_GEMM = S_DATA + STAGES * STAGE_BYTES;   // 82,944 (same as before)
static_assert(S_DATA + 2 * 128 * EPAD * 4 <= SMEM_GEMM, "fp32 agg arrays fit");

__global__ __launch_bounds__(256, 2)
void gemm_kernel(const __grid_constant__ CUtensorMap tA,
                 const __grid_constant__ CUtensorMap tB0,
                 const __grid_constant__ CUtensorMap tB1,
                 const __grid_constant__ CUtensorMap tB2,
                 const float* __restrict__ bf, const float* __restrict__ bi,
                 const float* __restrict__ bh)
{
    extern __shared__ char smem[];
    const uint32_t sb = smem_u32(smem);
    const int tid  = threadIdx.x;
    const int lane = tid & 31;
    const int wid  = tid >> 5;
    const int wm   = wid & 3;          // 0..3
    const int wn   = wid >> 2;         // 0..1
    const int m0   = blockIdx.x * 128;
    const int n0   = blockIdx.y * 64;
    const int gr   = lane >> 2;        // 0..7
    const int gc   = lane & 3;         // 0..3

    // ldmatrix lane geometry, SW64: addr = row*64 + (colbyte ^ (((row>>1)&3)<<4))
    const int a_r   = wm * 32 + ((lane >> 3) & 1) * 8 + (lane & 7);
    const int a_kb  = (lane >> 4) * 16;              // 0 or 16 bytes
    const int b_nr  = wn * 32 + ((lane >> 4) & 1) * 8 + (lane & 7);
    const int b_kb  = ((lane >> 3) & 1) * 16;
    const int mska  = ((a_r >> 1) & 3) << 4;         // SW64 mask (row bits [2:1])
    const int mskb  = ((b_nr >> 1) & 3) << 4;

    // barriers: full[s] at sb+s*16, empty[s] at sb+s*16+8
    if (tid == 0) {
        for (int s = 0; s < STAGES; s++) {
            mbar_init(sb + s * 16, 1);       // full: tx-based
            mbar_init(sb + s * 16 + 8, 8);   // empty: one arrive per warp
        }
    }
    __syncthreads();
    if (tid == 0) {
        for (int s = 0; s < STAGES; s++) {
            mbar_expect_tx(sb + s * 16, STAGE_BYTES);
            const uint32_t st = sb + S_DATA + s * STAGE_BYTES;
            tma_2d(st,         &tA,  s * 32, m0, sb + s * 16);
            tma_2d(st +  8192, &tB0, s * 32, n0, sb + s * 16);
            tma_2d(st + 12288, &tB1, s * 32, n0, sb + s * 16);
            tma_2d(st + 16384, &tB2, s * 32, n0, sb + s * 16);
        }
    }

    float acc[3][2][4][4];
    #pragma unroll
    for (int m = 0; m < 3; m++)
        #pragma unroll
        for (int i = 0; i < 2; i++)
            #pragma unroll
            for (int j = 0; j < 4; j++)
                #pragma unroll
                for (int r = 0; r < 4; r++) acc[m][i][j][r] = 0.0f;

    for (int kt = 0; kt < 32; kt++) {
        const int s  = kt & 3;
        const int ph = (kt >> 2) & 1;
        mbar_wait(sb + s * 16, ph);
        const uint32_t uA = sb + S_DATA + s * STAGE_BYTES;

        #pragma unroll
        for (int ks = 0; ks < 2; ks++) {
            const int axk = (ks * 32 + a_kb) ^ mska;
            const int bxk = (ks * 32 + b_kb) ^ mskb;
            uint32_t af[2][4];
            ldsm4(af[0], uA + a_r * 64 + axk);
            ldsm4(af[1], uA + (a_r + 16) * 64 + axk);
            #pragma unroll
            for (int mat = 0; mat < 3; mat++) {
                const uint32_t uB = uA + 8192 + mat * 4096 + b_nr * 64;
                uint32_t bb[2][4];
                ldsm4(bb[0], uB + bxk);
                ldsm4(bb[1], uB + 16 * 64 + bxk);
                // early release: last smem read of this stage just completed
                if (ks == 1 && mat == 2) {
                    __syncwarp();
                    if (lane == 0) mbar_arrive(sb + s * 16 + 8);
                }
                #pragma unroll
                for (int ns = 0; ns < 4; ns++) {
                    const uint32_t b0 = bb[ns >> 1][(ns & 1) * 2];
                    const uint32_t b1 = bb[ns >> 1][(ns & 1) * 2 + 1];
                    mma16(acc[mat][0][ns], af[0], b0, b1);
                    mma16(acc[mat][1][ns], af[1], b0, b1);
                }
            }
        }

        if (tid == 0 && kt + STAGES < 32) {
            mbar_wait(sb + s * 16 + 8, ph);            // all warps released stage s
            mbar_expect_tx(sb + s * 16, STAGE_BYTES);
            const uint32_t st = sb + S_DATA + s * STAGE_BYTES;
            const int kk = (kt + STAGES) * 32;
            tma_2d(st,         &tA,  kk, m0, sb + s * 16);
            tma_2d(st +  8192, &tB0, kk, n0, sb + s * 16);
            tma_2d(st + 12288, &tB1, kk, n0, sb + s * 16);
            tma_2d(st + 16384, &tB2, kk, n0, sb + s * 16);
        }
    }
    __syncthreads();   // all warps done before stage smem reuse

    // ---- epilogue (round-12): gates -> direct gmem half2 + fp32 smem for agg ----
    float* smf = (float*)(smem + S_DATA);              // 128 x EPAD floats
    float* smv = smf + 128 * EPAD;
    __half2* gfv_base = g_fv + (long long)m0 * Hdim + n0;
    #pragma unroll
    for (int ns = 0; ns < 4; ns++) {
        const int col = wn * 32 + ns * 8 + gc * 2;
        const float2 Bf = *(const float2*)(bf + n0 + col);
        const float2 Bi = *(const float2*)(bi + n0 + col);
        const float2 Bh = *(const float2*)(bh + n0 + col);
        #pragma unroll
        for (int ms = 0; ms < 2; ms++) {
            #pragma unroll
            for (int hf = 0; hf < 2; hf++) {
                const int row = wm * 32 + ms * 16 + gr + hf * 8;
                float fv[2][2];
                #pragma unroll
                for (int e = 0; e < 2; e++) {
                    const float zf = acc[0][ms][ns][hf * 2 + e] + (e ? Bf.y : Bf.x);
                    const float zi = acc[1][ms][ns][hf * 2 + e] + (e ? Bi.y : Bi.x);
                    const float zh = acc[2][ms][ns][hf * 2 + e] + (e ? Bh.y : Bh.x);
                    const float a  = __expf(-zf);
                    const float b  = __expf(-zi);
                    const float rd = __fdividef(1.0f, 2.0f + a + b);
                    const float c  = __expf(zh);
                    const float gg = (zh >= 0.0f) ? (zh + 0.5f) : __fdividef(c, 1.0f + c);
                    fv[e][0] = (1.0f + b) * rd;          // f
                    fv[e][1] = (1.0f + a) * rd * gg;     // v
                }
                uint2 pk;
                pk.x = f2h2(fv[0][0], fv[0][1]);
                pk.y = f2h2(fv[1][0], fv[1][1]);
                *(uint2*)(gfv_base + (long long)row * Hdim + col) = pk;
                *(float2*)(smf + row * EPAD + col) = make_float2(fv[0][0], fv[1][0]);
                *(float2*)(smv + row * EPAD + col) = make_float2(fv[0][1], fv[1][1]);
            }
        }
    }
    __syncthreads();

    // ---- fused chunk-scan pass 1 ----
    {
        const int ci  = tid >> 6;          // 0..3
        const int col = tid & 63;
        const int b   = m0 >> 12;
        const int cb  = (m0 & 4095) >> 5;
        float F = 1.0f, V = 0.0f;
        #pragma unroll 8
        for (int r = 0; r < 32; r++) {
            const int row = ci * 32 + r;
            const float f = smf[row * EPAD + col];
            const float v = smv[row * EPAD + col];
            V = fmaf(f, V, v);
            F *= f;
        }
        const int o = (b * NC + cb + ci) * Hdim + n0 + col;
        g_F[o] = F;
        g_V[o] = V;
    }
}

// ---------------- chunk prefix: warp-parallel affine scan ----------------
__global__ __launch_bounds__(1024)
void chunk_prefix_kernel(const float* __restrict__ h0)
{
    const int g = blockIdx.x * 32 + (threadIdx.x >> 5);
    const int l = threadIdx.x & 31;
    const int b = g >> 10;
    const int h = g & 1023;

    float Fk[4], Vk[4];
    #pragma unroll
    for (int k = 0; k < 4; k++) {
        const int o = (b * NC + 4 * l + k) * Hdim + h;
        Fk[k] = g_F[o];
        Vk[k] = g_V[o];
    }
    float Fa = Fk[0], Va = Vk[0];
    #pragma unroll
    for (int k = 1; k < 4; k++) { Va = fmaf(Fk[k], Va, Vk[k]); Fa *= Fk[k]; }
    #pragma unroll
    for (int d = 1; d < 32; d <<= 1) {
        const float Fo = __shfl_up_sync(0xFFFFFFFF, Fa, d);
        const float Vo = __shfl_up_sync(0xFFFFFFFF, Va, d);
        if (l >= d) { Va = fmaf(Fa, Vo, Va); Fa *= Fo; }
    }
    float Fe = __shfl_up_sync(0xFFFFFFFF, Fa, 1);
    float Ve = __shfl_up_sync(0xFFFFFFFF, Va, 1);
    if (l == 0) { Fe = 1.0f; Ve = 0.0f; }

    const float x = h0[b * Hdim + h];
    const float h0p = (x >= 0.0f) ? (x + 0.5f) : sigmf(x);
    float hs = fmaf(Fe, h0p, Ve);
    #pragma unroll
    for (int k = 0; k < 4; k++) {
        g_Hs[(b * NC + 4 * l + k) * Hdim + h] = hs;
        hs = fmaf(Fk[k], hs, Vk[k]);
    }
}

// ---------------- apply: within-chunk scan, write output ----------------
__global__ __launch_bounds__(1024)
void apply_kernel(float* __restrict__ out)
{
    const int h = threadIdx.x;
    const int c = blockIdx.x;
    const int b = blockIdx.y;
    float run = g_Hs[(b * NC + c) * Hdim + h];
    const __half2* fvp = g_fv + ((long long)(b * Tt + c * LCc)) * Hdim + h;
    float* op = out + ((long long)(b * Tt + c * LCc)) * Hdim + h;
    #pragma unroll 8
    for (int l = 0; l < LCc; l++) {
        const float2 fv = __half22float2(fvp[(long long)l * Hdim]);
        run = fmaf(fv.x, run, fv.y);
        op[(long long)l * Hdim] = run;
    }
}

// ---------------- host ----------------
typedef CUresult (*encode_fn_t)(CUtensorMap*, CUtensorMapDataType, cuuint32_t, void*,
                                const cuuint64_t*, const cuuint64_t*, const cuuint32_t*,
                                const cuuint32_t*, CUtensorMapInterleave, CUtensorMapSwizzle,
                                CUtensorMapL2promotion, CUtensorMapFloatOOBfill);

static void make_map(encode_fn_t enc, CUtensorMap* m, const void* ptr,
                     unsigned long long rows, unsigned box_rows)
{
    cuuint64_t dims[2]    = {1024ull, rows};
    cuuint64_t strides[1] = {2048ull};                 // fp16 row bytes
    cuuint32_t box[2]     = {32u, box_rows};           // 32 halves = 64B = SW64 atom
    cuuint32_t estr[2]    = {1u, 1u};
    enc(m, CU_TENSOR_MAP_DATA_TYPE_FLOAT16, 2, (void*)ptr, dims, strides, box, estr,
        CU_TENSOR_MAP_INTERLEAVE_NONE, CU_TENSOR_MAP_SWIZZLE_64B,
        CU_TENSOR_MAP_L2_PROMOTION_L2_128B, CU_TENSOR_MAP_FLOAT_OOB_FILL_NONE);
}

extern "C" void kernel_launch(void* const* d_in, const int* in_sizes, int n_in,
                              void* d_out, int out_size)
{
    (void)in_sizes; (void)n_in; (void)out_size;
    const float* x  = (const float*)d_in[0];
    const float* h0 = (const float*)d_in[1];
    const float* Wf = (const float*)d_in[2];
    const float* bf = (const float*)d_in[3];
    const float* Wi = (const float*)d_in[4];
    const float* bi = (const float*)d_in[5];
    const float* Wh = (const float*)d_in[6];
    const float* bh = (const float*)d_in[7];
    float* out = (float*)d_out;

    void* xh = nullptr; void* wh = nullptr;
    cudaGetSymbolAddress(&xh, g_xh);
    cudaGetSymbolAddress(&wh, g_wh);

    void* fp = nullptr;
    cudaDriverEntryPointQueryResult qres;
    cudaGetDriverEntryPointByVersion("cuTensorMapEncodeTiled", &fp, 12000,
                                     cudaEnableDefault, &qres);
    encode_fn_t enc = (encode_fn_t)fp;

    CUtensorMap tA, tB0, tB1, tB2;
    make_map(enc, &tA,  xh,                              16384ull, 128u);
    make_map(enc, &tB0, (__half*)wh,                     1024ull,  64u);
    make_map(enc, &tB1, (__half*)wh + 1024 * 1024,       1024ull,  64u);
    make_map(enc, &tB2, (__half*)wh + 2 * 1024 * 1024,   1024ull,  64u);

    cudaFuncSetAttribute(gemm_kernel,
                         cudaFuncAttributeMaxDynamicSharedMemorySize, SMEM_GEMM);

    // launch order: GEMM is 4th launch (ncu sampling lands there)
    cvt_x_kernel<<<4096, 256>>>((const float4*)x, 0);
    cvt_x_kernel<<<4096, 256>>>((const float4*)x, 1048576);
    cvt_w_kernel<<<512, 256>>>((const float4*)Wf, (const float4*)Wi, (const float4*)Wh);
    gemm_kernel<<<dim3(128, 16), 256, SMEM_GEMM>>>(tA, tB0, tB1, tB2, bf, bi, bh);
    chunk_prefix_kernel<<<128, 1024>>>(h0);
    apply_kernel<<<dim3(NC, Bb), 1024>>>(out);
}

// round 14
// speedup vs baseline: 1.1243x; 1.1243x over previous
#include <cuda_runtime.h>
#include <cuda.h>
#include <cuda_fp16.h>
#include <cstdint>
#include <math.h>

// ---------------- problem constants ----------------
constexpr int Bb = 4, Tt = 4096, Hdim = 1024;
constexpr int Mtot = Bb * Tt;                         // 16384
constexpr long long PLANE = (long long)Mtot * Hdim;   // 16,777,216
constexpr int NC = 128, LCc = 32;
constexpr int EPAD = 66;                              // even pad

// Scratch (device globals; allocation-free)
__device__ __align__(16) __half2 g_fv[PLANE];         // packed (f, v) per element
__device__ __align__(1024) __half g_xh[PLANE];        // fp16 x
__device__ __align__(1024) __half g_wh[3u * 1024 * 1024]; // fp16 Wf|Wi|Wh
__device__ float g_F [Bb * NC * Hdim];
__device__ float g_V [Bb * NC * Hdim];
__device__ float g_Hs[Bb * NC * Hdim];

// ---------------- PTX helpers (base sm_103 target only) ----------------
__device__ __forceinline__ uint32_t smem_u32(const void* p) {
    uint32_t a;
    asm("{ .reg .u64 t; cvta.to.shared.u64 t, %1; cvt.u32.u64 %0, t; }" : "=r"(a) : "l"(p));
    return a;
}
__device__ __forceinline__ void mbar_init(uint32_t a, uint32_t cnt) {
    asm volatile("mbarrier.init.shared.b64 [%0], %1;" :: "r"(a), "r"(cnt) : "memory");
}
__device__ __forceinline__ void mbar_arrive(uint32_t a) {
    asm volatile("mbarrier.arrive.shared.b64 _, [%0];" :: "r"(a) : "memory");
}
__device__ __forceinline__ void mbar_expect_tx(uint32_t a, uint32_t bytes) {
    asm volatile("mbarrier.arrive.expect_tx.shared.b64 _, [%0], %1;" :: "r"(a), "r"(bytes) : "memory");
}
__device__ __forceinline__ void mbar_wait(uint32_t a, uint32_t parity) {
    asm volatile(
        "{\n\t.reg .pred P;\n\t"
        "WL%=:\n\t"
        "mbarrier.try_wait.parity.acquire.cta.shared::cta.b64 P, [%0], %1, 0x989680;\n\t"
        "@!P bra WL%=;\n\t}"
        :: "r"(a), "r"(parity) : "memory");
}
__device__ __forceinline__ void tma_2d(uint32_t dst, const CUtensorMap* m, int x, int y, uint32_t mbar) {
    asm volatile(
        "cp.async.bulk.tensor.2d.shared::cta.global.tile.mbarrier::complete_tx::bytes "
        "[%0], [%1, {%2, %3}], [%4];"
        :: "r"(dst), "l"(m), "r"(x), "r"(y), "r"(mbar) : "memory");
}
__device__ __forceinline__ void ldsm4(uint32_t* r, uint32_t addr) {
    asm volatile("ldmatrix.sync.aligned.m8n8.x4.shared.b16 {%0,%1,%2,%3}, [%4];"
                 : "=r"(r[0]), "=r"(r[1]), "=r"(r[2]), "=r"(r[3]) : "r"(addr));
}
__device__ __forceinline__ void mma16(float* d, const uint32_t* a, uint32_t b0, uint32_t b1) {
    asm volatile(
        "mma.sync.aligned.m16n8k16.row.col.f32.f16.f16.f32 "
        "{%0,%1,%2,%3}, {%4,%5,%6,%7}, {%8,%9}, {%0,%1,%2,%3};"
        : "+f"(d[0]), "+f"(d[1]), "+f"(d[2]), "+f"(d[3])
        : "r"(a[0]), "r"(a[1]), "r"(a[2]), "r"(a[3]), "r"(b0), "r"(b1));
}
__device__ __forceinline__ uint32_t f2h2(float a, float b) {
    __half2 h = __floats2half2_rn(a, b);
    return *reinterpret_cast<uint32_t*>(&h);
}

// ---------------- scalar math ----------------
__device__ __forceinline__ float sigmf(float x) {
    float e = expf(-fabsf(x));
    return (x >= 0.0f) ? 1.0f / (1.0f + e) : e / (1.0f + e);
}

// ---------------- prep: single fused conversion kernel ----------------
// blocks [0, 8192): x plane (2,097,152 groups of 8 floats)
// blocks [8192, 8704): all three W mats (131,072 groups each)
__global__ __launch_bounds__(256)
void cvt_all_kernel(const float4* __restrict__ x,
                    const float4* __restrict__ wf, const float4* __restrict__ wi,
                    const float4* __restrict__ wh) {
    if (blockIdx.x < 8192) {
        const int g = blockIdx.x * 256 + threadIdx.x;
        const float4 v0 = x[2 * g];
        const float4 v1 = x[2 * g + 1];
        uint4 o;
        o.x = f2h2(v0.x, v0.y); o.y = f2h2(v0.z, v0.w);
        o.z = f2h2(v1.x, v1.y); o.w = f2h2(v1.z, v1.w);
        ((uint4*)g_xh)[g] = o;
    } else {
        const int g = (blockIdx.x - 8192) * 256 + threadIdx.x;
        const float4* src[3] = {wf, wi, wh};
        #pragma unroll
        for (int mat = 0; mat < 3; mat++) {
            const float4 v0 = src[mat][2 * g];
            const float4 v1 = src[mat][2 * g + 1];
            uint4 o;
            o.x = f2h2(v0.x, v0.y); o.y = f2h2(v0.z, v0.w);
            o.z = f2h2(v1.x, v1.y); o.w = f2h2(v1.z, v1.w);
            ((uint4*)g_wh)[mat * 131072 + g] = o;
        }
    }
}

// ---------------- fused GEMM (fp16 HMMA) + gates + chunk aggregates ----------------
// (round-12 proven configuration: 2-stage SW128 ring, BK=64, early release)
constexpr int STAGES = 2;
constexpr int STAGE_BYTES = 40960;                   // A 16K + 3x B 8K
constexpr int S_DATA = 1024;
constexpr int SMEM_GEMM = S_DATA + STAGES * STAGE_BYTES;   // 82,944
static_assert(S_DATA + 2 * 128 * EPAD * 4 <= SMEM_GEMM, "fp32 agg arrays fit");

__global__ __launch_bounds__(256, 2)
void gemm_kernel(const __grid_constant__ CUtensorMap tA,
                 const __grid_constant__ CUtensorMap tB0,
                 const __grid_constant__ CUtensorMap tB1,
                 const __grid_constant__ CUtensorMap tB2,
                 const float* __restrict__ bf, const float* __restrict__ bi,
                 const float* __restrict__ bh)
{
    extern __shared__ char smem[];
    const uint32_t sb = smem_u32(smem);
    const int tid  = threadIdx.x;
    const int lane = tid & 31;
    const int wid  = tid >> 5;
    const int wm   = wid & 3;          // 0..3
    const int wn   = wid >> 2;         // 0..1
    const int m0   = blockIdx.x * 128;
    const int n0   = blockIdx.y * 64;
    const int gr   = lane >> 2;        // 0..7
    const int gc   = lane & 3;         // 0..3

    // ldmatrix lane geometry (SW128: addr = row*128 + (colbyte ^ ((row&7)<<4)))
    const int a_r   = wm * 32 + ((lane >> 3) & 1) * 8 + (lane & 7);
    const int a_kb  = (lane >> 4) * 16;
    const int b_nr  = wn * 32 + ((lane >> 4) & 1) * 8 + (lane & 7);
    const int b_kb  = ((lane >> 3) & 1) * 16;
    const int msk   = (lane & 7) << 4;

    // barriers: full[s] at sb+s*16, empty[s] at sb+s*16+8
    if (tid == 0) {
        for (int s = 0; s < STAGES; s++) {
            mbar_init(sb + s * 16, 1);       // full: tx-based
            mbar_init(sb + s * 16 + 8, 8);   // empty: one arrive per warp
        }
    }
    __syncthreads();
    if (tid == 0) {
        for (int s = 0; s < STAGES; s++) {
            mbar_expect_tx(sb + s * 16, STAGE_BYTES);
            const uint32_t st = sb + S_DATA + s * STAGE_BYTES;
            tma_2d(st,         &tA,  s * 64, m0, sb + s * 16);
            tma_2d(st + 16384, &tB0, s * 64, n0, sb + s * 16);
            tma_2d(st + 24576, &tB1, s * 64, n0, sb + s * 16);
            tma_2d(st + 32768, &tB2, s * 64, n0, sb + s * 16);
        }
    }

    float acc[3][2][4][4];
    #pragma unroll
    for (int m = 0; m < 3; m++)
        #pragma unroll
        for (int i = 0; i < 2; i++)
            #pragma unroll
            for (int j = 0; j < 4; j++)
                #pragma unroll
                for (int r = 0; r < 4; r++) acc[m][i][j][r] = 0.0f;

    const uint32_t stg0 = sb + S_DATA;
    const uint32_t stg1 = sb + S_DATA + STAGE_BYTES;

    for (int kt = 0; kt < 16; kt++) {
        const int s  = kt & 1;
        const int ph = (kt >> 1) & 1;
        mbar_wait(sb + s * 16, ph);
        const uint32_t uA = s ? stg1 : stg0;

        #pragma unroll
        for (int ks = 0; ks < 4; ks++) {
            const int axk = (ks * 32 + a_kb) ^ msk;
            const int bxk = (ks * 32 + b_kb) ^ msk;
            uint32_t af[2][4];
            ldsm4(af[0], uA + a_r * 128 + axk);
            ldsm4(af[1], uA + (a_r + 16) * 128 + axk);
            #pragma unroll
            for (int mat = 0; mat < 3; mat++) {
                const uint32_t uB = uA + 16384 + mat * 8192 + b_nr * 128;
                uint32_t bb[2][4];
                ldsm4(bb[0], uB + bxk);
                ldsm4(bb[1], uB + 16 * 128 + bxk);
                // early release: last smem read of this stage just completed
                if (ks == 3 && mat == 2) {
                    __syncwarp();
                    if (lane == 0) mbar_arrive(sb + s * 16 + 8);
                }
                #pragma unroll
                for (int ns = 0; ns < 4; ns++) {
                    const uint32_t b0 = bb[ns >> 1][(ns & 1) * 2];
                    const uint32_t b1 = bb[ns >> 1][(ns & 1) * 2 + 1];
                    mma16(acc[mat][0][ns], af[0], b0, b1);
                    mma16(acc[mat][1][ns], af[1], b0, b1);
                }
            }
        }

        if (tid == 0 && kt + STAGES < 16) {
            mbar_wait(sb + s * 16 + 8, ph);            // all warps released stage s
            mbar_expect_tx(sb + s * 16, STAGE_BYTES);
            const uint32_t st = s ? stg1 : stg0;
            const int kk = (kt + STAGES) * 64;
            tma_2d(st,         &tA,  kk, m0, sb + s * 16);
            tma_2d(st + 16384, &tB0, kk, n0, sb + s * 16);
            tma_2d(st + 24576, &tB1, kk, n0, sb + s * 16);
            tma_2d(st + 32768, &tB2, kk, n0, sb + s * 16);
        }
    }
    __syncthreads();   // all warps done before stage smem reuse

    // ---- epilogue: gates -> direct gmem half2 + fp32 smem for aggregates ----
    float* smf = (float*)(smem + S_DATA);              // 128 x EPAD floats
    float* smv = smf + 128 * EPAD;
    __half2* gfv_base = g_fv + (long long)m0 * Hdim + n0;
    #pragma unroll
    for (int ns = 0; ns < 4; ns++) {
        const int col = wn * 32 + ns * 8 + gc * 2;
        const float2 Bf = *(const float2*)(bf + n0 + col);
        const float2 Bi = *(const float2*)(bi + n0 + col);
        const float2 Bh = *(const float2*)(bh + n0 + col);
        #pragma unroll
        for (int ms = 0; ms < 2; ms++) {
            #pragma unroll
            for (int hf = 0; hf < 2; hf++) {
                const int row = wm * 32 + ms * 16 + gr + hf * 8;
                float fv[2][2];
                #pragma unroll
                for (int e = 0; e < 2; e++) {
                    const float zf = acc[0][ms][ns][hf * 2 + e] + (e ? Bf.y : Bf.x);
                    const float zi = acc[1][ms][ns][hf * 2 + e] + (e ? Bi.y : Bi.x);
                    const float zh = acc[2][ms][ns][hf * 2 + e] + (e ? Bh.y : Bh.x);
                    const float a  = __expf(-zf);
                    const float b  = __expf(-zi);
                    const float rd = __fdividef(1.0f, 2.0f + a + b);
                    const float c  = __expf(zh);
                    const float gg = (zh >= 0.0f) ? (zh + 0.5f) : __fdividef(c, 1.0f + c);
                    fv[e][0] = (1.0f + b) * rd;          // f
                    fv[e][1] = (1.0f + a) * rd * gg;     // v
                }
                uint2 pk;
                pk.x = f2h2(fv[0][0], fv[0][1]);
                pk.y = f2h2(fv[1][0], fv[1][1]);
                *(uint2*)(gfv_base + (long long)row * Hdim + col) = pk;
                *(float2*)(smf + row * EPAD + col) = make_float2(fv[0][0], fv[1][0]);
                *(float2*)(smv + row * EPAD + col) = make_float2(fv[0][1], fv[1][1]);
            }
        }
    }
    __syncthreads();

    // ---- fused chunk-scan pass 1 ----
    {
        const int ci  = tid >> 6;          // 0..3
        const int col = tid & 63;
        const int b   = m0 >> 12;
        const int cb  = (m0 & 4095) >> 5;
        float F = 1.0f, V = 0.0f;
        #pragma unroll 8
        for (int r = 0; r < 32; r++) {
            const int row = ci * 32 + r;
            const float f = smf[row * EPAD + col];
            const float v = smv[row * EPAD + col];
            V = fmaf(f, V, v);
            F *= f;
        }
        const int o = (b * NC + cb + ci) * Hdim + n0 + col;
        g_F[o] = F;
        g_V[o] = V;
    }
}

// ---------------- chunk prefix: warp-parallel affine scan ----------------
__global__ __launch_bounds__(1024)
void chunk_prefix_kernel(const float* __restrict__ h0)
{
    const int g = blockIdx.x * 32 + (threadIdx.x >> 5);
    const int l = threadIdx.x & 31;
    const int b = g >> 10;
    const int h = g & 1023;

    float Fk[4], Vk[4];
    #pragma unroll
    for (int k = 0; k < 4; k++) {
        const int o = (b * NC + 4 * l + k) * Hdim + h;
        Fk[k] = g_F[o];
        Vk[k] = g_V[o];
    }
    float Fa = Fk[0], Va = Vk[0];
    #pragma unroll
    for (int k = 1; k < 4; k++) { Va = fmaf(Fk[k], Va, Vk[k]); Fa *= Fk[k]; }
    #pragma unroll
    for (int d = 1; d < 32; d <<= 1) {
        const float Fo = __shfl_up_sync(0xFFFFFFFF, Fa, d);
        const float Vo = __shfl_up_sync(0xFFFFFFFF, Va, d);
        if (l >= d) { Va = fmaf(Fa, Vo, Va); Fa *= Fo; }
    }
    float Fe = __shfl_up_sync(0xFFFFFFFF, Fa, 1);
    float Ve = __shfl_up_sync(0xFFFFFFFF, Va, 1);
    if (l == 0) { Fe = 1.0f; Ve = 0.0f; }

    const float x = h0[b * Hdim + h];
    const float h0p = (x >= 0.0f) ? (x + 0.5f) : sigmf(x);
    float hs = fmaf(Fe, h0p, Ve);
    #pragma unroll
    for (int k = 0; k < 4; k++) {
        g_Hs[(b * NC + 4 * l + k) * Hdim + h] = hs;
        hs = fmaf(Fk[k], hs, Vk[k]);
    }
}

// ---------------- apply: within-chunk scan, 2 columns per thread ----------------
__global__ __launch_bounds__(512)
void apply_kernel(float* __restrict__ out)
{
    const int h2 = threadIdx.x;            // 0..511: columns 2*h2, 2*h2+1
    const int c  = blockIdx.x;
    const int b  = blockIdx.y;
    const int base_h = 2 * h2;
    float run0 = g_Hs[(b * NC + c) * Hdim + base_h];
    float run1 = g_Hs[(b * NC + c) * Hdim + base_h + 1];
    const uint2* fvp = (const uint2*)(g_fv + ((long long)(b * Tt + c * LCc)) * Hdim + base_h);
    float* op = out + ((long long)(b * Tt + c * LCc)) * Hdim + base_h;
    #pragma unroll 8
    for (int l = 0; l < LCc; l++) {
        const uint2 pk = fvp[(long long)l * (Hdim / 2)];
        const float2 fv0 = __half22float2(*(const __half2*)&pk.x);
        const float2 fv1 = __half22float2(*(const __half2*)&pk.y);
        run0 = fmaf(fv0.x, run0, fv0.y);
        run1 = fmaf(fv1.x, run1, fv1.y);
        *(float2*)(op + (long long)l * Hdim) = make_float2(run0, run1);
    }
}

// ---------------- host ----------------
typedef CUresult (*encode_fn_t)(CUtensorMap*, CUtensorMapDataType, cuuint32_t, void*,
                                const cuuint64_t*, const cuuint64_t*, const cuuint32_t*,
                                const cuuint32_t*, CUtensorMapInterleave, CUtensorMapSwizzle,
                                CUtensorMapL2promotion, CUtensorMapFloatOOBfill);

static void make_map(encode_fn_t enc, CUtensorMap* m, const void* ptr,
                     unsigned long long rows, unsigned box_rows)
{
    cuuint64_t dims[2]    = {1024ull, rows};
    cuuint64_t strides[1] = {2048ull};                 // fp16 row bytes
    cuuint32_t box[2]     = {64u, box_rows};           // 64 halves = 128B = SW128 atom
    cuuint32_t estr[2]    = {1u, 1u};
    enc(m, CU_TENSOR_MAP_DATA_TYPE_FLOAT16, 2, (void*)ptr, dims, strides, box, estr,
        CU_TENSOR_MAP_INTERLEAVE_NONE, CU_TENSOR_MAP_SWIZZLE_128B,
        CU_TENSOR_MAP_L2_PROMOTION_L2_128B, CU_TENSOR_MAP_FLOAT_OOB_FILL_NONE);
}

extern "C" void kernel_launch(void* const* d_in, const int* in_sizes, int n_in,
                              void* d_out, int out_size)
{
    (void)in_sizes; (void)n_in; (void)out_size;
    const float* x  = (const float*)d_in[0];
    const float* h0 = (const float*)d_in[1];
    const float* Wf = (const float*)d_in[2];
    const float* bf = (const float*)d_in[3];
    const float* Wi = (const float*)d_in[4];
    const float* bi = (const float*)d_in[5];
    const float* Wh = (const float*)d_in[6];
    const float* bh = (const float*)d_in[7];
    float* out = (float*)d_out;

    void* xh = nullptr; void* wh = nullptr;
    cudaGetSymbolAddress(&xh, g_xh);
    cudaGetSymbolAddress(&wh, g_wh);

    void* fp = nullptr;
    cudaDriverEntryPointQueryResult qres;
    cudaGetDriverEntryPointByVersion("cuTensorMapEncodeTiled", &fp, 12000,
                                     cudaEnableDefault, &qres);
    encode_fn_t enc = (encode_fn_t)fp;

    CUtensorMap tA, tB0, tB1, tB2;
    make_map(enc, &tA,  xh,                              16384ull, 128u);
    make_map(enc, &tB0, (__half*)wh,                     1024ull,  64u);
    make_map(enc, &tB1, (__half*)wh + 1024 * 1024,       1024ull,  64u);
    make_map(enc, &tB2, (__half*)wh + 2 * 1024 * 1024,   1024ull,  64u);

    cudaFuncSetAttribute(gemm_kernel,
                         cudaFuncAttributeMaxDynamicSharedMemorySize, SMEM_GEMM);

    cvt_all_kernel<<<8704, 256>>>((const float4*)x, (const float4*)Wf,
                                  (const float4*)Wi, (const float4*)Wh);
    gemm_kernel<<<dim3(128, 16), 256, SMEM_GEMM>>>(tA, tB0, tB1, tB2, bf, bi, bh);
    chunk_prefix_kernel<<<128, 1024>>>(h0);
    apply_kernel<<<dim3(NC, Bb), 512>>>(out);
}